// round 1
// baseline (speedup 1.0000x reference)
#include <cuda_runtime.h>
#include <math.h>

// Problem shape (fixed by the dataset)
#define BB_L 200
#define BB_D 128
#define BB_H 100
#define N_THREADS 256

// SMEM layout (in floats)
//  xs  : x transposed as f32x2 pairs, [128 d][105 l-pairs] u64  -> 26880 floats
//  wk  : Wk padded [128 d][128 j]                                -> 16384 floats
//  cj  : bk[j] + (q @ Wq)[j], padded to 128                      ->   128
//  vv  : v[j] padded to 128 (zeros beyond 100)                   ->   128
//  qs  : q[b][:]                                                 ->   128
//  sc  : a_l = exp(score_l)*mask_l, 208 (l padded)               ->   208
//  mk  : mask per l, 208                                         ->   208
//  red : block-reduce scratch                                    ->     8
#define OFF_XS   0
#define OFF_WK   26880
#define OFF_CJ   (OFF_WK + 16384)
#define OFF_VV   (OFF_CJ + 128)
#define OFF_QS   (OFF_VV + 128)
#define OFF_SC   (OFF_QS + 128)
#define OFF_MK   (OFF_SC + 208)
#define OFF_RED  (OFF_MK + 208)
#define SMEM_FLOATS (OFF_RED + 8)
#define SMEM_BYTES (SMEM_FLOATS * 4)

__device__ __forceinline__ float tanh_fast(float x) {
    float y;
    asm("tanh.approx.f32 %0, %1;" : "=f"(y) : "f"(x));
    return y;
}

__device__ __forceinline__ unsigned long long dup2(float v) {
    unsigned long long r;
    asm("mov.b64 %0, {%1, %1};" : "=l"(r) : "f"(v));
    return r;
}

__device__ __forceinline__ unsigned long long pack2(float lo, float hi) {
    unsigned long long r;
    asm("mov.b64 %0, {%1, %2};" : "=l"(r) : "f"(lo), "f"(hi));
    return r;
}

__device__ __forceinline__ unsigned long long fma2(unsigned long long a,
                                                   unsigned long long b,
                                                   unsigned long long c) {
    unsigned long long d;
    asm("fma.rn.f32x2 %0, %1, %2, %3;" : "=l"(d) : "l"(a), "l"(b), "l"(c));
    return d;
}

__device__ __forceinline__ float2 unpack2(unsigned long long v) {
    float2 f;
    asm("mov.b64 {%0, %1}, %2;" : "=f"(f.x), "=f"(f.y) : "l"(v));
    return f;
}

// GEMM + score epilogue for NP l-pairs (warp-cooperative; lanes = j chunks)
template <int NP>
__device__ __forceinline__ void gemm_group(
    const unsigned long long* __restrict__ xs,
    const float* __restrict__ wk,
    const float* __restrict__ cj,
    const float* __restrict__ vv,
    float* __restrict__ sc,
    const float* __restrict__ mk,
    int pair0, int lane)
{
    unsigned long long acc[NP][4];
#pragma unroll
    for (int p = 0; p < NP; ++p)
#pragma unroll
        for (int k = 0; k < 4; ++k) acc[p][k] = 0ULL;

#pragma unroll 4
    for (int d = 0; d < 128; ++d) {
        const float* wr = wk + d * 128 + lane;
        unsigned long long W[4];
#pragma unroll
        for (int k = 0; k < 4; ++k) W[k] = dup2(wr[32 * k]);
#pragma unroll
        for (int p = 0; p < NP; ++p) {
            unsigned long long xv = xs[d * 105 + pair0 + p];  // broadcast within warp
#pragma unroll
            for (int k = 0; k < 4; ++k) acc[p][k] = fma2(xv, W[k], acc[p][k]);
        }
    }

#pragma unroll
    for (int p = 0; p < NP; ++p) {
        float slo = 0.f, shi = 0.f;
#pragma unroll
        for (int k = 0; k < 4; ++k) {
            int j = lane + 32 * k;
            float c = cj[j];
            float vw = vv[j];          // zero for j >= 100 -> padded chunk harmless
            float2 a = unpack2(acc[p][k]);
            slo += tanh_fast(a.x + c) * vw;
            shi += tanh_fast(a.y + c) * vw;
        }
#pragma unroll
        for (int o = 16; o; o >>= 1) {
            slo += __shfl_xor_sync(0xffffffffu, slo, o);
            shi += __shfl_xor_sync(0xffffffffu, shi, o);
        }
        if (lane == 0) {
            int l0 = 2 * (pair0 + p);
            sc[l0]     = expf(slo) * mk[l0];      // faithful (non-stable) exp-normalize
            sc[l0 + 1] = expf(shi) * mk[l0 + 1];
        }
    }
}

__global__ void __launch_bounds__(N_THREADS, 1)
mxqa_kernel(const float* __restrict__ x, const float* __restrict__ q,
            const float* __restrict__ Wk, const float* __restrict__ bk,
            const float* __restrict__ Wq, const float* __restrict__ v,
            float* __restrict__ out)
{
    extern __shared__ float sm[];
    float* xs_f = sm + OFF_XS;
    unsigned long long* xs = reinterpret_cast<unsigned long long*>(sm + OFF_XS);
    float* wk = sm + OFF_WK;
    float* cj = sm + OFF_CJ;
    float* vv = sm + OFF_VV;
    float* qs = sm + OFF_QS;
    float* sc = sm + OFF_SC;
    float* mk = sm + OFF_MK;
    float* red = sm + OFF_RED;

    const int tid = threadIdx.x;
    const int lane = tid & 31;
    const int warp = tid >> 5;
    const int b = blockIdx.x;

    // ---------------- Phase 1: stage weights / init ----------------
    for (int i = tid; i < 128 * 128; i += N_THREADS) {
        int d = i >> 7, j = i & 127;
        wk[i] = (j < BB_H) ? Wk[d * BB_H + j] : 0.f;
    }
    if (tid < 128) {
        qs[tid] = q[(long long)b * 128 + tid];
        vv[tid] = (tid < BB_H) ? v[tid] : 0.f;
    }
    if (tid < 208) mk[tid] = 0.f;
    // zero padded l-pairs 100..104 (l = 200..209)
    for (int i = tid; i < 128 * 5; i += N_THREADS) {
        int d = i / 5, lp = 100 + (i % 5);
        xs[d * 105 + lp] = 0ULL;
    }
    __syncthreads();

    // ---------------- Phase 2: cj = bk + q@Wq, and x load/transpose ----------------
    if (tid < 128) {
        float s = 0.f;
        if (tid < BB_H) {
#pragma unroll 8
            for (int d = 0; d < 128; ++d) s += qs[d] * Wq[d * BB_H + tid];
            s += bk[tid];
        }
        cj[tid] = s;
    }

    const float* xb = x + (long long)b * (BB_L * BB_D);
    // thread handles a 2(l) x 2(d) micro-tile: coalesced LDG.64, paired STS.64
    for (int u = tid; u < 100 * 64; u += N_THREADS) {
        int d2 = u & 63;
        int lp = u >> 6;
        const float2 a0 = *reinterpret_cast<const float2*>(xb + (2 * lp) * 128 + 2 * d2);
        const float2 a1 = *reinterpret_cast<const float2*>(xb + (2 * lp + 1) * 128 + 2 * d2);
        xs[(2 * d2) * 105 + lp]     = pack2(a0.x, a1.x);
        xs[(2 * d2 + 1) * 105 + lp] = pack2(a0.y, a1.y);
        if (a0.x != 0.f || a0.y != 0.f) mk[2 * lp] = 1.f;       // benign race (all write 1)
        if (a1.x != 0.f || a1.y != 0.f) mk[2 * lp + 1] = 1.f;
    }
    __syncthreads();

    // ---------------- Phase 3: fused GEMM + tanh + score ----------------
    // warp w owns l-pairs [13w, 13w+13): groups of 4,4,4,1
    {
        const int pb = warp * 13;
        gemm_group<4>(xs, wk, cj, vv, sc, mk, pb + 0, lane);
        gemm_group<4>(xs, wk, cj, vv, sc, mk, pb + 4, lane);
        gemm_group<4>(xs, wk, cj, vv, sc, mk, pb + 8, lane);
        gemm_group<1>(xs, wk, cj, vv, sc, mk, pb + 12, lane);
    }
    __syncthreads();

    // ---------------- Phase 4: normalization factor ----------------
    {
        float s = (tid < 208) ? sc[tid] : 0.f;
#pragma unroll
        for (int o = 16; o; o >>= 1) s += __shfl_xor_sync(0xffffffffu, s, o);
        if (lane == 0) red[warp] = s;
    }
    __syncthreads();
    if (tid == 0) {
        float t = 0.f;
#pragma unroll
        for (int w = 0; w < 8; ++w) t += red[w];
        red[0] = 1.f / (t + 1e-7f);
    }
    __syncthreads();
    const float winv = red[0];

    // ---------------- Phase 5: out[b][d] = winv * sum_l a_l * x[l][d] ----------------
    {
        const int d = tid & 127;
        const int half = tid >> 7;
        float acc = 0.f;
        const int l0 = half * 104;
#pragma unroll 4
        for (int l = l0; l < l0 + 104; ++l)
            acc += sc[l] * xs_f[d * 210 + l];   // xs viewed as floats: (d,l) at d*210+l
        float* part = wk;  // safe to reuse after syncthreads above
        part[tid] = acc;
    }
    __syncthreads();
    if (tid < 128)
        out[(long long)b * 128 + tid] = (wk[tid] + wk[tid + 128]) * winv;
}

extern "C" void kernel_launch(void* const* d_in, const int* in_sizes, int n_in,
                              void* d_out, int out_size)
{
    const float* x  = (const float*)d_in[0];
    const float* q  = (const float*)d_in[1];
    const float* Wk = (const float*)d_in[2];
    const float* bk = (const float*)d_in[3];
    const float* Wq = (const float*)d_in[4];
    const float* v  = (const float*)d_in[5];
    float* out = (float*)d_out;

    const int B = in_sizes[1] / BB_D;  // q is [B, 128]

    cudaFuncSetAttribute(mxqa_kernel, cudaFuncAttributeMaxDynamicSharedMemorySize, SMEM_BYTES);
    mxqa_kernel<<<B, N_THREADS, SMEM_BYTES>>>(x, q, Wk, bk, Wq, v, out);
}

// round 2
// speedup vs baseline: 1.1068x; 1.1068x over previous
#include <cuda_runtime.h>
#include <math.h>

// Problem shape (fixed by the dataset)
#define BB_L 200
#define BB_D 128
#define BB_H 100
#define N_THREADS 512
#define N_WARPS 16

// SMEM layout (in floats)
#define OFF_XS   0                      // x transposed f32x2 pairs [128 d][105 lp] u64 -> 26880 f
#define OFF_WK   26880                  // Wk padded [128 d][128 j] -> 16384 f
#define OFF_CJ   (OFF_WK + 16384)       // bk + q@Wq (padded 128)
#define OFF_VV   (OFF_CJ + 128)         // v padded 128
#define OFF_QS   (OFF_VV + 128)         // q row
#define OFF_SC   (OFF_QS + 128)         // exp(score)*mask, 208
#define OFF_MK   (OFF_SC + 208)         // mask, 208
#define OFF_RED  (OFF_MK + 208)         // reduce scratch, 16
#define SMEM_FLOATS (OFF_RED + 16)
#define SMEM_BYTES (SMEM_FLOATS * 4)

__device__ __forceinline__ float tanh_fast(float x) {
    float y;
    asm("tanh.approx.f32 %0, %1;" : "=f"(y) : "f"(x));
    return y;
}

__device__ __forceinline__ unsigned long long dup2(float v) {
    unsigned long long r;
    asm("mov.b64 %0, {%1, %1};" : "=l"(r) : "f"(v));
    return r;
}

__device__ __forceinline__ unsigned long long pack2(float lo, float hi) {
    unsigned long long r;
    asm("mov.b64 %0, {%1, %2};" : "=l"(r) : "f"(lo), "f"(hi));
    return r;
}

__device__ __forceinline__ unsigned long long fma2(unsigned long long a,
                                                   unsigned long long b,
                                                   unsigned long long c) {
    unsigned long long d;
    asm("fma.rn.f32x2 %0, %1, %2, %3;" : "=l"(d) : "l"(a), "l"(b), "l"(c));
    return d;
}

__device__ __forceinline__ float2 unpack2(unsigned long long v) {
    float2 f;
    asm("mov.b64 {%0, %1}, %2;" : "=f"(f.x), "=f"(f.y) : "l"(v));
    return f;
}

// GEMM + score epilogue for NP l-pairs (warp-cooperative; lanes = j chunks)
template <int NP>
__device__ __forceinline__ void gemm_group(
    const unsigned long long* __restrict__ xs,
    const float* __restrict__ wk,
    const float* __restrict__ cj,
    const float* __restrict__ vv,
    float* __restrict__ sc,
    const float* __restrict__ mk,
    int pair0, int lane)
{
    unsigned long long acc[NP][4];
#pragma unroll
    for (int p = 0; p < NP; ++p)
#pragma unroll
        for (int k = 0; k < 4; ++k) acc[p][k] = 0ULL;

#pragma unroll 4
    for (int d = 0; d < 128; ++d) {
        const float* wr = wk + d * 128 + lane;
        unsigned long long W[4];
#pragma unroll
        for (int k = 0; k < 4; ++k) W[k] = dup2(wr[32 * k]);
#pragma unroll
        for (int p = 0; p < NP; ++p) {
            unsigned long long xv = xs[d * 105 + pair0 + p];  // broadcast within warp
#pragma unroll
            for (int k = 0; k < 4; ++k) acc[p][k] = fma2(xv, W[k], acc[p][k]);
        }
    }

#pragma unroll
    for (int p = 0; p < NP; ++p) {
        float slo = 0.f, shi = 0.f;
#pragma unroll
        for (int k = 0; k < 4; ++k) {
            int j = lane + 32 * k;
            float c = cj[j];
            float vw = vv[j];          // zero for j >= 100 -> padded chunk harmless
            float2 a = unpack2(acc[p][k]);
            slo += tanh_fast(a.x + c) * vw;
            shi += tanh_fast(a.y + c) * vw;
        }
#pragma unroll
        for (int o = 16; o; o >>= 1) {
            slo += __shfl_xor_sync(0xffffffffu, slo, o);
            shi += __shfl_xor_sync(0xffffffffu, shi, o);
        }
        if (lane == 0) {
            int l0 = 2 * (pair0 + p);
            sc[l0]     = expf(slo) * mk[l0];      // faithful (non-stable) exp-normalize
            sc[l0 + 1] = expf(shi) * mk[l0 + 1];
        }
    }
}

__global__ void __launch_bounds__(N_THREADS, 1)
mxqa_kernel(const float* __restrict__ x, const float* __restrict__ q,
            const float* __restrict__ Wk, const float* __restrict__ bk,
            const float* __restrict__ Wq, const float* __restrict__ v,
            float* __restrict__ out)
{
    extern __shared__ float sm[];
    float* xs_f = sm + OFF_XS;
    unsigned long long* xs = reinterpret_cast<unsigned long long*>(sm + OFF_XS);
    float* wk = sm + OFF_WK;
    float* cj = sm + OFF_CJ;
    float* vv = sm + OFF_VV;
    float* qs = sm + OFF_QS;
    float* sc = sm + OFF_SC;
    float* mk = sm + OFF_MK;
    float* red = sm + OFF_RED;

    const int tid = threadIdx.x;
    const int lane = tid & 31;
    const int warp = tid >> 5;
    const int b = blockIdx.x;

    // ---------------- Phase 1: stage weights / init ----------------
    for (int i = tid; i < 128 * 128; i += N_THREADS) {
        int d = i >> 7, j = i & 127;
        wk[i] = (j < BB_H) ? Wk[d * BB_H + j] : 0.f;
    }
    if (tid < 128) {
        qs[tid] = q[(long long)b * 128 + tid];
        vv[tid] = (tid < BB_H) ? v[tid] : 0.f;
    }
    if (tid < 208) mk[tid] = 0.f;
    // zero padded l-pairs 100..104 (l = 200..209)
    for (int i = tid; i < 128 * 5; i += N_THREADS) {
        int d = i / 5, lp = 100 + (i % 5);
        xs[d * 105 + lp] = 0ULL;
    }
    __syncthreads();

    // ---------------- Phase 2: cj = bk + q@Wq, and x load/transpose ----------------
    if (tid < 128) {
        float s = 0.f;
        if (tid < BB_H) {
#pragma unroll 8
            for (int d = 0; d < 128; ++d) s += qs[d] * Wq[d * BB_H + tid];
            s += bk[tid];
        }
        cj[tid] = s;
    }

    const float* xb = x + (long long)b * (BB_L * BB_D);
    // thread handles a 2(l) x 2(d) micro-tile: coalesced LDG.64, paired STS.64
    for (int u = tid; u < 100 * 64; u += N_THREADS) {
        int d2 = u & 63;
        int lp = u >> 6;
        const float2 a0 = *reinterpret_cast<const float2*>(xb + (2 * lp) * 128 + 2 * d2);
        const float2 a1 = *reinterpret_cast<const float2*>(xb + (2 * lp + 1) * 128 + 2 * d2);
        xs[(2 * d2) * 105 + lp]     = pack2(a0.x, a1.x);
        xs[(2 * d2 + 1) * 105 + lp] = pack2(a0.y, a1.y);
        if (a0.x != 0.f || a0.y != 0.f) mk[2 * lp] = 1.f;       // benign race (all write 1)
        if (a1.x != 0.f || a1.y != 0.f) mk[2 * lp + 1] = 1.f;
    }
    __syncthreads();

    // ---------------- Phase 3: fused GEMM + tanh + score ----------------
    // 16 warps; warps 0-3 own 7 l-pairs, warps 4-15 own 6 (4*7 + 12*6 = 100)
    if (warp < 4) {
        gemm_group<7>(xs, wk, cj, vv, sc, mk, 7 * warp, lane);
    } else {
        gemm_group<6>(xs, wk, cj, vv, sc, mk, 28 + 6 * (warp - 4), lane);
    }
    __syncthreads();

    // ---------------- Phase 4: normalization factor ----------------
    {
        float s = (tid < 208) ? sc[tid] : 0.f;
#pragma unroll
        for (int o = 16; o; o >>= 1) s += __shfl_xor_sync(0xffffffffu, s, o);
        if (lane == 0) red[warp] = s;
    }
    __syncthreads();
    if (tid == 0) {
        float t = 0.f;
#pragma unroll
        for (int w = 0; w < N_WARPS; ++w) t += red[w];
        red[0] = 1.f / (t + 1e-7f);
    }
    __syncthreads();
    const float winv = red[0];

    // ---------------- Phase 5: out[b][d] = winv * sum_l a_l * x[l][d] ----------------
    {
        const int d = tid & 127;
        const int quarter = tid >> 7;          // 0..3
        float acc = 0.f;
        const int l0 = quarter * 52;
#pragma unroll 4
        for (int l = l0; l < l0 + 52; ++l)
            acc += sc[l] * xs_f[d * 210 + l];   // xs viewed as floats: (d,l) at d*210+l
        float* part = wk;  // safe to reuse after syncthreads above
        part[tid] = acc;
    }
    __syncthreads();
    if (tid < 128)
        out[(long long)b * 128 + tid] =
            (wk[tid] + wk[tid + 128] + wk[tid + 256] + wk[tid + 384]) * winv;
}

extern "C" void kernel_launch(void* const* d_in, const int* in_sizes, int n_in,
                              void* d_out, int out_size)
{
    const float* x  = (const float*)d_in[0];
    const float* q  = (const float*)d_in[1];
    const float* Wk = (const float*)d_in[2];
    const float* bk = (const float*)d_in[3];
    const float* Wq = (const float*)d_in[4];
    const float* v  = (const float*)d_in[5];
    float* out = (float*)d_out;

    const int B = in_sizes[1] / BB_D;  // q is [B, 128]

    cudaFuncSetAttribute(mxqa_kernel, cudaFuncAttributeMaxDynamicSharedMemorySize, SMEM_BYTES);
    mxqa_kernel<<<B, N_THREADS, SMEM_BYTES>>>(x, q, Wk, bk, Wq, v, out);
}

// round 4
// speedup vs baseline: 1.7928x; 1.6198x over previous
#include <cuda_runtime.h>
#include <cstdint>
#include <math.h>

#define BB_L 200
#define BB_D 128
#define BB_H 100
#define NT 512

#define XS_PITCH 132
#define WK_PITCH 108

// SMEM layout (float indices)
#define OFF_XS  0                        // x fp32 [208 rows][132]  -> 27456 f
#define OFF_WK  (208 * XS_PITCH)         // Wk tf32 [128][108]      -> 13824 f
#define OFF_CV  (OFF_WK + 128 * WK_PITCH) // (cj, vv) float2 [112]  ->   224 f
#define OFF_QS  (OFF_CV + 224)           // q row                    ->   128 f
#define OFF_SC  (OFF_QS + 128)           // exp(score)*mask, 208
#define OFF_MK  (OFF_SC + 208)           // mask, 208
#define OFF_RED (OFF_MK + 208)           // 16
#define SMEM_FLOATS (OFF_RED + 16)
#define SMEM_BYTES (SMEM_FLOATS * 4)

__device__ __forceinline__ uint32_t to_tf32(float f) {
    uint32_t r;
    asm("cvt.rna.tf32.f32 %0, %1;" : "=r"(r) : "f"(f));
    return r;
}
__device__ __forceinline__ float tanh_fast(float x) {
    float y;
    asm("tanh.approx.f32 %0, %1;" : "=f"(y) : "f"(x));
    return y;
}
__device__ __forceinline__ void mma_tf32(float* c,
                                         uint32_t a0, uint32_t a1, uint32_t a2, uint32_t a3,
                                         uint32_t b0, uint32_t b1) {
    asm volatile(
        "mma.sync.aligned.m16n8k8.row.col.f32.tf32.tf32.f32 "
        "{%0,%1,%2,%3}, {%4,%5,%6,%7}, {%8,%9}, {%0,%1,%2,%3};"
        : "+f"(c[0]), "+f"(c[1]), "+f"(c[2]), "+f"(c[3])
        : "r"(a0), "r"(a1), "r"(a2), "r"(a3), "r"(b0), "r"(b1));
}

__global__ void __launch_bounds__(NT, 1)
mxqa_mma_kernel(const float* __restrict__ x, const float* __restrict__ q,
                const float* __restrict__ Wk, const float* __restrict__ bk,
                const float* __restrict__ Wq, const float* __restrict__ v,
                float* __restrict__ out)
{
    extern __shared__ float sm[];
    float* xs = sm + OFF_XS;
    uint32_t* wks = reinterpret_cast<uint32_t*>(sm + OFF_WK);
    float2* cvv = reinterpret_cast<float2*>(sm + OFF_CV);
    float* qs = sm + OFF_QS;
    float* sc = sm + OFF_SC;
    float* mk = sm + OFF_MK;
    float* red = sm + OFF_RED;

    const int tid = threadIdx.x;
    const int lane = tid & 31;
    const int warp = tid >> 5;
    const int b = blockIdx.x;
    const int g = lane >> 2;     // group id 0..7 (row within fragment)
    const int t = lane & 3;      // thread-in-group 0..3 (col/k slot)

    // ---------------- Phase 1: staging ----------------
    if (tid < 128) qs[tid] = q[(long long)b * 128 + tid];
    if (tid < 208) { sc[tid] = 0.f; mk[tid] = 0.f; }

    // zero A pad rows l = 200..207 (contiguous 8*132 floats)
    for (int i = tid; i < 8 * XS_PITCH; i += NT) xs[200 * XS_PITCH + i] = 0.f;

    // Wk -> tf32 SMEM [d][j], pitch 108, j padded to 104 with zeros
    for (int i = tid; i < 128 * 104; i += NT) {
        int d = i / 104;
        int j = i - d * 104;
        float w = (j < BB_H) ? Wk[d * BB_H + j] : 0.f;
        wks[d * WK_PITCH + j] = to_tf32(w);
    }

    // x -> fp32 SMEM [l][d], pitch 132; compute mask
    {
        const float4* xb4 = reinterpret_cast<const float4*>(x + (long long)b * (BB_L * BB_D));
        for (int i = tid; i < BB_L * 32; i += NT) {
            int l = i >> 5;
            int gg = i & 31;                       // float4 index, d = 4*gg
            float4 v4 = xb4[i];
            *reinterpret_cast<float4*>(xs + l * XS_PITCH + 4 * gg) = v4;
            if (v4.x != 0.f || v4.y != 0.f || v4.z != 0.f || v4.w != 0.f) mk[l] = 1.f;
        }
    }
    __syncthreads();

    // ---------------- Phase 2: GEMM (warps 0-12) || cj (warps 13-15) ----------------
    float acc[13][4];
    if (warp < 13) {
        const int m0 = warp * 16;
        const float* xA0 = xs + (m0 + g) * XS_PITCH;
        const float* xA1 = xs + (m0 + g + 8) * XS_PITCH;
#pragma unroll
        for (int nt = 0; nt < 13; ++nt)
#pragma unroll
            for (int k = 0; k < 4; ++k) acc[nt][k] = 0.f;

#pragma unroll 2
        for (int ks = 0; ks < 16; ++ks) {
            const int k0 = 8 * ks;
            uint32_t a0 = to_tf32(xA0[k0 + t]);
            uint32_t a1 = to_tf32(xA1[k0 + t]);
            uint32_t a2 = to_tf32(xA0[k0 + t + 4]);
            uint32_t a3 = to_tf32(xA1[k0 + t + 4]);
            const uint32_t* b0p = wks + (k0 + t) * WK_PITCH + g;
            const uint32_t* b1p = wks + (k0 + t + 4) * WK_PITCH + g;
#pragma unroll
            for (int nt = 0; nt < 13; ++nt)
                mma_tf32(acc[nt], a0, a1, a2, a3, b0p[nt * 8], b1p[nt * 8]);
        }
    } else {
        // cj[j] = bk[j] + sum_d q[d]*Wq[d][j]; vv[j] = v[j] (pad to 104)
        const int jt = tid - 13 * 32;   // 0..95
        for (int j = jt; j < 104; j += 96) {
            float s = 0.f, vw = 0.f;
            if (j < BB_H) {
                s = bk[j];
#pragma unroll 8
                for (int d = 0; d < 128; ++d) s += qs[d] * Wq[d * BB_H + j];
                vw = v[j];
            }
            cvv[j] = make_float2(s, vw);
        }
    }
    __syncthreads();

    // ---------------- Phase 3: epilogue on fragments ----------------
    if (warp < 13) {
        float s0 = 0.f, s1 = 0.f;
#pragma unroll
        for (int nt = 0; nt < 13; ++nt) {
            int j0 = nt * 8 + 2 * t;
            float2 c0 = cvv[j0];
            float2 c1 = cvv[j0 + 1];
            s0 += tanh_fast(acc[nt][0] + c0.x) * c0.y;
            s0 += tanh_fast(acc[nt][1] + c1.x) * c1.y;
            s1 += tanh_fast(acc[nt][2] + c0.x) * c0.y;
            s1 += tanh_fast(acc[nt][3] + c1.x) * c1.y;
        }
        s0 += __shfl_xor_sync(0xffffffffu, s0, 1);
        s0 += __shfl_xor_sync(0xffffffffu, s0, 2);
        s1 += __shfl_xor_sync(0xffffffffu, s1, 1);
        s1 += __shfl_xor_sync(0xffffffffu, s1, 2);
        if (t == 0) {
            int l0 = warp * 16 + g;
            int l1 = l0 + 8;
            if (l0 < BB_L) sc[l0] = expf(s0) * mk[l0];
            if (l1 < BB_L) sc[l1] = expf(s1) * mk[l1];
        }
    }
    __syncthreads();

    // ---------------- Phase 4: normalization factor ----------------
    {
        float s = (tid < 208) ? sc[tid] : 0.f;
#pragma unroll
        for (int o = 16; o; o >>= 1) s += __shfl_xor_sync(0xffffffffu, s, o);
        if (lane == 0) red[warp] = s;
    }
    __syncthreads();
    if (tid == 0) {
        float tsum = 0.f;
#pragma unroll
        for (int w = 0; w < 16; ++w) tsum += red[w];
        red[0] = 1.f / (tsum + 1e-7f);
    }
    __syncthreads();
    const float winv = red[0];

    // ---------------- Phase 5: out[b][d] = winv * sum_l sc[l] * x[l][d] ----------------
    {
        const int d = tid & 127;
        const int quarter = tid >> 7;
        float a = 0.f;
        const int l0 = quarter * 50;
#pragma unroll 2
        for (int l = l0; l < l0 + 50; ++l)
            a += sc[l] * xs[l * XS_PITCH + d];
        // partial sums: reuse the Wk region (GEMM is done; synced above)
        sm[OFF_WK + tid] = a;
    }
    __syncthreads();
    if (tid < 128)
        out[(long long)b * 128 + tid] =
            (sm[OFF_WK + tid] + sm[OFF_WK + tid + 128] +
             sm[OFF_WK + tid + 256] + sm[OFF_WK + tid + 384]) * winv;
}

extern "C" void kernel_launch(void* const* d_in, const int* in_sizes, int n_in,
                              void* d_out, int out_size)
{
    const float* x  = (const float*)d_in[0];
    const float* q  = (const float*)d_in[1];
    const float* Wk = (const float*)d_in[2];
    const float* bk = (const float*)d_in[3];
    const float* Wq = (const float*)d_in[4];
    const float* v  = (const float*)d_in[5];
    float* out = (float*)d_out;

    const int B = in_sizes[1] / BB_D;  // q is [B, 128]

    cudaFuncSetAttribute(mxqa_mma_kernel, cudaFuncAttributeMaxDynamicSharedMemorySize, SMEM_BYTES);
    mxqa_mma_kernel<<<B, NT, SMEM_BYTES>>>(x, q, Wk, bk, Wq, v, out);
}

// round 5
// speedup vs baseline: 2.3338x; 1.3018x over previous
#include <cuda_runtime.h>
#include <cstdint>
#include <math.h>

#define BB_L 200
#define BB_D 128
#define BB_H 100
#define NT 1024

#define XS_PITCH 132
#define WK_PITCH 104   // == 8 mod 32 -> conflict-free B-fragment loads

// SMEM layout (float indices)
#define OFF_XS  0                          // x fp32 [208][132]      -> 27456 f
#define OFF_WK  (208 * XS_PITCH)           // Wk tf32 [128][104]     -> 13312 f
#define OFF_CV  (OFF_WK + 128 * WK_PITCH)  // (cj, vv) float2 [112]  ->   224 f
#define OFF_QS  (OFF_CV + 224)             // q row                  ->   128 f
#define OFF_SC  (OFF_QS + 128)             // exp(score)*mask, 208
#define OFF_MK  (OFF_SC + 208)             // mask, 208
#define OFF_SCP (OFF_MK + 208)             // partial scores [208][2] -> 416 f
#define OFF_RED (OFF_SCP + 416)            // 16
#define SMEM_FLOATS (OFF_RED + 16)
#define SMEM_BYTES (SMEM_FLOATS * 4)

__device__ __forceinline__ uint32_t to_tf32(float f) {
    uint32_t r;
    asm("cvt.rna.tf32.f32 %0, %1;" : "=r"(r) : "f"(f));
    return r;
}
__device__ __forceinline__ float tanh_fast(float x) {
    float y;
    asm("tanh.approx.f32 %0, %1;" : "=f"(y) : "f"(x));
    return y;
}
__device__ __forceinline__ void mma_tf32(float* c,
                                         uint32_t a0, uint32_t a1, uint32_t a2, uint32_t a3,
                                         uint32_t b0, uint32_t b1) {
    asm volatile(
        "mma.sync.aligned.m16n8k8.row.col.f32.tf32.tf32.f32 "
        "{%0,%1,%2,%3}, {%4,%5,%6,%7}, {%8,%9}, {%0,%1,%2,%3};"
        : "+f"(c[0]), "+f"(c[1]), "+f"(c[2]), "+f"(c[3])
        : "r"(a0), "r"(a1), "r"(a2), "r"(a3), "r"(b0), "r"(b1));
}

__global__ void __launch_bounds__(NT, 1)
mxqa_mma_kernel(const float* __restrict__ x, const float* __restrict__ q,
                const float* __restrict__ Wk, const float* __restrict__ bk,
                const float* __restrict__ Wq, const float* __restrict__ v,
                float* __restrict__ out)
{
    extern __shared__ float sm[];
    float* xs = sm + OFF_XS;
    uint32_t* wks = reinterpret_cast<uint32_t*>(sm + OFF_WK);
    float2* cvv = reinterpret_cast<float2*>(sm + OFF_CV);
    float* qs = sm + OFF_QS;
    float* sc = sm + OFF_SC;
    float* mk = sm + OFF_MK;
    float* scp = sm + OFF_SCP;
    float* red = sm + OFF_RED;

    const int tid = threadIdx.x;
    const int lane = tid & 31;
    const int warp = tid >> 5;
    const int b = blockIdx.x;
    const int g = lane >> 2;     // fragment row group 0..7
    const int t = lane & 3;      // k/col slot 0..3

    // ---------------- Phase 1: staging ----------------
    if (tid < 128) qs[tid] = q[(long long)b * 128 + tid];
    if (tid < 208) { sc[tid] = 0.f; mk[tid] = 0.f; }

    // zero A pad rows l = 200..207
    if (tid < 8 * XS_PITCH) xs[200 * XS_PITCH + tid] = 0.f;

    // Wk -> tf32 SMEM [d][j], pitch 104, j padded to 104 with zeros
    for (int i = tid; i < 128 * 104; i += NT) {
        int d = i / 104;
        int j = i - d * 104;
        float w = (j < BB_H) ? Wk[d * BB_H + j] : 0.f;
        wks[d * WK_PITCH + j] = to_tf32(w);
    }

    // x -> fp32 SMEM [l][d], pitch 132; compute mask
    {
        const float4* xb4 = reinterpret_cast<const float4*>(x + (long long)b * (BB_L * BB_D));
        for (int i = tid; i < BB_L * 32; i += NT) {
            int l = i >> 5;
            int gg = i & 31;                       // float4 index, d = 4*gg
            float4 v4 = xb4[i];
            *reinterpret_cast<float4*>(xs + l * XS_PITCH + 4 * gg) = v4;
            if (v4.x != 0.f || v4.y != 0.f || v4.z != 0.f || v4.w != 0.f) mk[l] = 1.f;
        }
    }
    __syncthreads();

    // ---------------- Phase 2: GEMM (warps 0-25) || cj (warps 26-31) ----------------
    float acc[7][4];
    const int mt = warp >> 1;
    const int half = warp & 1;
    if (warp < 26) {
        const int m0 = mt * 16;
        const float* xr0 = xs + (m0 + g) * XS_PITCH;
        const float* xr1 = xr0 + 8 * XS_PITCH;
        const uint32_t* wb = wks + half * 48 + g;   // half1 covers nt 6..12 (nt6 dup, excluded later)
#pragma unroll
        for (int nt = 0; nt < 7; ++nt)
#pragma unroll
            for (int k = 0; k < 4; ++k) acc[nt][k] = 0.f;

#pragma unroll
        for (int ks = 0; ks < 16; ++ks) {
            const int k0 = 8 * ks;
            uint32_t a0 = to_tf32(xr0[k0 + t]);
            uint32_t a1 = to_tf32(xr1[k0 + t]);
            uint32_t a2 = to_tf32(xr0[k0 + t + 4]);
            uint32_t a3 = to_tf32(xr1[k0 + t + 4]);
            const uint32_t* b0r = wb + (k0 + t) * WK_PITCH;
            const uint32_t* b1r = b0r + 4 * WK_PITCH;
#pragma unroll
            for (int nt = 0; nt < 7; ++nt)
                mma_tf32(acc[nt], a0, a1, a2, a3, b0r[8 * nt], b1r[8 * nt]);
        }
    } else {
        // cj[j] = bk[j] + sum_d q[d]*Wq[d][j]; vv[j] = v[j] (pad to 104)
        const int j = tid - 26 * 32;   // 0..191, only j<104 active
        if (j < 104) {
            float s = 0.f, vw = 0.f;
            if (j < BB_H) {
                s = bk[j];
#pragma unroll 8
                for (int d = 0; d < 128; ++d) s += qs[d] * Wq[d * BB_H + j];
                vw = v[j];
            }
            cvv[j] = make_float2(s, vw);
        }
    }
    __syncthreads();

    // ---------------- Phase 3: epilogue on fragments (warps 0-25) ----------------
    if (warp < 26) {
        float s0 = 0.f, s1 = 0.f;
#pragma unroll
        for (int nt = 0; nt < 7; ++nt) {
            if (half && nt == 0) continue;          // nt6 duplicate column
            int j0 = half * 48 + nt * 8 + 2 * t;
            float2 c0 = cvv[j0];
            float2 c1 = cvv[j0 + 1];
            s0 += tanh_fast(acc[nt][0] + c0.x) * c0.y;
            s0 += tanh_fast(acc[nt][1] + c1.x) * c1.y;
            s1 += tanh_fast(acc[nt][2] + c0.x) * c0.y;
            s1 += tanh_fast(acc[nt][3] + c1.x) * c1.y;
        }
        s0 += __shfl_xor_sync(0xffffffffu, s0, 1);
        s0 += __shfl_xor_sync(0xffffffffu, s0, 2);
        s1 += __shfl_xor_sync(0xffffffffu, s1, 1);
        s1 += __shfl_xor_sync(0xffffffffu, s1, 2);
        if (t == 0) {
            int l0 = mt * 16 + g;
            scp[2 * l0 + half] = s0;
            scp[2 * (l0 + 8) + half] = s1;
        }
    }
    __syncthreads();

    // ---------------- Phase 4: combine halves, exp, normalize ----------------
    {
        float a = 0.f;
        if (tid < 208) {
            a = expf(scp[2 * tid] + scp[2 * tid + 1]) * mk[tid];
            sc[tid] = a;
        }
        if (warp < 7) {
#pragma unroll
            for (int o = 16; o; o >>= 1) a += __shfl_xor_sync(0xffffffffu, a, o);
            if (lane == 0) red[warp] = a;
        }
    }
    __syncthreads();
    if (tid == 0) {
        float tsum = 0.f;
#pragma unroll
        for (int w = 0; w < 7; ++w) tsum += red[w];
        red[0] = 1.f / (tsum + 1e-7f);
    }
    __syncthreads();
    const float winv = red[0];

    // ---------------- Phase 5: out[b][d] = winv * sum_l sc[l] * x[l][d] ----------------
    {
        const int d = tid & 127;
        const int oct = tid >> 7;            // 0..7
        float a = 0.f;
        const int l0 = oct * 25;
#pragma unroll 5
        for (int l = l0; l < l0 + 25; ++l)
            a += sc[l] * xs[l * XS_PITCH + d];
        sm[OFF_WK + tid] = a;                // reuse Wk region
    }
    __syncthreads();
    if (tid < 128) {
        float o = 0.f;
#pragma unroll
        for (int k = 0; k < 8; ++k) o += sm[OFF_WK + tid + 128 * k];
        out[(long long)b * 128 + tid] = o * winv;
    }
}

extern "C" void kernel_launch(void* const* d_in, const int* in_sizes, int n_in,
                              void* d_out, int out_size)
{
    const float* x  = (const float*)d_in[0];
    const float* q  = (const float*)d_in[1];
    const float* Wk = (const float*)d_in[2];
    const float* bk = (const float*)d_in[3];
    const float* Wq = (const float*)d_in[4];
    const float* v  = (const float*)d_in[5];
    float* out = (float*)d_out;

    const int B = in_sizes[1] / BB_D;  // q is [B, 128]

    cudaFuncSetAttribute(mxqa_mma_kernel, cudaFuncAttributeMaxDynamicSharedMemorySize, SMEM_BYTES);
    mxqa_mma_kernel<<<B, NT, SMEM_BYTES>>>(x, q, Wk, bk, Wq, v, out);
}

// round 6
// speedup vs baseline: 2.9359x; 1.2580x over previous
#include <cuda_runtime.h>
#include <cstdint>
#include <math.h>

#define BB_L 200
#define BB_D 128
#define BB_H 100
#define NT 1024

// paired A layout: row pitch 68 float2 (136 floats)
#define XA_PITCH2 68

// SMEM layout (float indices)
#define OFF_XA  0                           // x fp32 pairs [208][136]     -> 28288 f
#define OFF_WK  (208 * 136)                 // packed tf32 B [16*13*32] f2 -> 13312 f
#define OFF_CV  (OFF_WK + 13312)            // (cj, vv) float2 [112]       ->   224 f
#define OFF_QS  (OFF_CV + 224)              // q row                       ->   128 f
#define OFF_SC  (OFF_QS + 128)              // exp(score)*mask, 208
#define OFF_MK  (OFF_SC + 208)              // mask, 208
#define OFF_SCP (OFF_MK + 208)              // partial scores [208][2]     ->   416 f
#define OFF_RED (OFF_SCP + 416)             // 16
#define SMEM_FLOATS (OFF_RED + 16)
#define SMEM_BYTES (SMEM_FLOATS * 4)

// packed Wk: idx = ((ks*13 + nt)*8 + g)*4 + t  (float2 each), 16*13*8*4 = 6656
__device__ float2 g_wkp[6656];

__device__ __forceinline__ uint32_t to_tf32(float f) {
    uint32_t r;
    asm("cvt.rna.tf32.f32 %0, %1;" : "=r"(r) : "f"(f));
    return r;
}
__device__ __forceinline__ float tanh_fast(float x) {
    float y;
    asm("tanh.approx.f32 %0, %1;" : "=f"(y) : "f"(x));
    return y;
}
__device__ __forceinline__ void mma_tf32(float* c,
                                         uint32_t a0, uint32_t a1, uint32_t a2, uint32_t a3,
                                         uint32_t b0, uint32_t b1) {
    asm volatile(
        "mma.sync.aligned.m16n8k8.row.col.f32.tf32.tf32.f32 "
        "{%0,%1,%2,%3}, {%4,%5,%6,%7}, {%8,%9}, {%0,%1,%2,%3};"
        : "+f"(c[0]), "+f"(c[1]), "+f"(c[2]), "+f"(c[3])
        : "r"(a0), "r"(a1), "r"(a2), "r"(a3), "r"(b0), "r"(b1));
}

// ---------------- prep: pack Wk into MMA fragment order (tf32) ----------------
__global__ void pack_wk_kernel(const float* __restrict__ Wk) {
    int i = blockIdx.x * 256 + threadIdx.x;
    if (i >= 6656) return;
    int t = i & 3;
    int g = (i >> 2) & 7;
    int kn = i >> 5;            // ks*13 + nt
    int nt = kn % 13;
    int ks = kn / 13;
    int j = 8 * nt + g;
    int d0 = 8 * ks + t;
    float w0 = (j < BB_H) ? Wk[d0 * BB_H + j] : 0.f;
    float w1 = (j < BB_H) ? Wk[(d0 + 4) * BB_H + j] : 0.f;
    float2 p;
    p.x = __uint_as_float(to_tf32(w0));
    p.y = __uint_as_float(to_tf32(w1));
    g_wkp[i] = p;
}

__global__ void __launch_bounds__(NT, 1)
mxqa_mma_kernel(const float* __restrict__ x, const float* __restrict__ q,
                const float* __restrict__ bk,
                const float* __restrict__ Wq, const float* __restrict__ v,
                float* __restrict__ out)
{
    extern __shared__ float sm[];
    float* xa = sm + OFF_XA;                       // paired fp32 x
    float2* cvv = reinterpret_cast<float2*>(sm + OFF_CV);
    float* qs = sm + OFF_QS;
    float* sc = sm + OFF_SC;
    float* mk = sm + OFF_MK;
    float* scp = sm + OFF_SCP;
    float* red = sm + OFF_RED;

    const int tid = threadIdx.x;
    const int lane = tid & 31;
    const int warp = tid >> 5;
    const int b = blockIdx.x;
    const int g = lane >> 2;     // fragment row group 0..7
    const int t = lane & 3;      // k/col slot 0..3

    // ---------------- Phase 1: staging ----------------
    if (tid < 128) qs[tid] = q[(long long)b * 128 + tid];
    if (tid < 208) { sc[tid] = 0.f; mk[tid] = 0.f; }

    // zero A pad rows l = 200..207 (8 * 136 = 1088 floats)
    if (tid < 1088) xa[200 * 136 + tid] = 0.f;

    // packed Wk: straight copy (3328 float4)
    {
        const float4* src = reinterpret_cast<const float4*>(g_wkp);
        float4* dst = reinterpret_cast<float4*>(sm + OFF_WK);
        for (int i = tid; i < 3328; i += NT) dst[i] = src[i];
    }

    // x -> paired fp32 SMEM; unit u = (l, ks) covering 8 floats; compute mask
    {
        const float4* xb4 = reinterpret_cast<const float4*>(x + (long long)b * (BB_L * BB_D));
        float4* xa4 = reinterpret_cast<float4*>(xa);
        for (int u = tid; u < BB_L * 16; u += NT) {
            int l = u >> 4;
            int ks = u & 15;
            float4 f0 = xb4[2 * u];
            float4 f1 = xb4[2 * u + 1];
            float4 o0, o1;   // pairs (x[8k+t], x[8k+t+4])
            o0.x = f0.x; o0.y = f1.x; o0.z = f0.y; o0.w = f1.y;
            o1.x = f0.z; o1.y = f1.z; o1.z = f0.w; o1.w = f1.w;
            xa4[l * 34 + 2 * ks] = o0;
            xa4[l * 34 + 2 * ks + 1] = o1;
            if (f0.x != 0.f || f0.y != 0.f || f0.z != 0.f || f0.w != 0.f ||
                f1.x != 0.f || f1.y != 0.f || f1.z != 0.f || f1.w != 0.f)
                mk[l] = 1.f;   // benign race, all write 1
        }
    }
    __syncthreads();

    // ---------------- Phase 2: GEMM (warps 0-25) || cj (warps 26-31) ----------------
    float acc[7][4];
    const int mt = warp >> 1;
    const int half = warp & 1;
    if (warp < 26) {
        const int m0 = mt * 16;
        const float2* pa0 = reinterpret_cast<const float2*>(xa) + (m0 + g) * XA_PITCH2 + t;
        const float2* pa1 = pa0 + 8 * XA_PITCH2;
        // B: uint2 at ((ks*13 + half*6 + nt)*8 + g)*4 + t
        const uint2* pb = reinterpret_cast<const uint2*>(sm + OFF_WK)
                          + (half * 6) * 32 + g * 4 + t;
#pragma unroll
        for (int nt = 0; nt < 7; ++nt)
#pragma unroll
            for (int k = 0; k < 4; ++k) acc[nt][k] = 0.f;

#pragma unroll
        for (int ks = 0; ks < 16; ++ks) {
            float2 p0 = pa0[4 * ks];
            float2 p1 = pa1[4 * ks];
            uint32_t a0 = to_tf32(p0.x);
            uint32_t a1 = to_tf32(p1.x);
            uint32_t a2 = to_tf32(p0.y);
            uint32_t a3 = to_tf32(p1.y);
            const uint2* pbk = pb + ks * 13 * 32;
#pragma unroll
            for (int nt = 0; nt < 7; ++nt) {
                uint2 bb = pbk[nt * 32];
                mma_tf32(acc[nt], a0, a1, a2, a3, bb.x, bb.y);
            }
        }
    } else {
        // cj[j] = bk[j] + sum_d q[d]*Wq[d][j]; vv[j] = v[j] (pad to 104)
        const int j = tid - 26 * 32;   // 0..191, only j<104 active
        if (j < 104) {
            float s = 0.f, vw = 0.f;
            if (j < BB_H) {
                s = bk[j];
#pragma unroll 8
                for (int d = 0; d < 128; ++d) s += qs[d] * Wq[d * BB_H + j];
                vw = v[j];
            }
            cvv[j] = make_float2(s, vw);
        }
    }
    __syncthreads();

    // ---------------- Phase 3: epilogue on fragments (warps 0-25) ----------------
    if (warp < 26) {
        float s0 = 0.f, s1 = 0.f;
#pragma unroll
        for (int nt = 0; nt < 7; ++nt) {
            if (half && nt == 0) continue;          // nt6 duplicate column
            int j0 = half * 48 + nt * 8 + 2 * t;
            float2 c0 = cvv[j0];
            float2 c1 = cvv[j0 + 1];
            s0 += tanh_fast(acc[nt][0] + c0.x) * c0.y;
            s0 += tanh_fast(acc[nt][1] + c1.x) * c1.y;
            s1 += tanh_fast(acc[nt][2] + c0.x) * c0.y;
            s1 += tanh_fast(acc[nt][3] + c1.x) * c1.y;
        }
        s0 += __shfl_xor_sync(0xffffffffu, s0, 1);
        s0 += __shfl_xor_sync(0xffffffffu, s0, 2);
        s1 += __shfl_xor_sync(0xffffffffu, s1, 1);
        s1 += __shfl_xor_sync(0xffffffffu, s1, 2);
        if (t == 0) {
            int l0 = mt * 16 + g;
            scp[2 * l0 + half] = s0;
            scp[2 * (l0 + 8) + half] = s1;
        }
    }
    __syncthreads();

    // ---------------- Phase 4: combine halves, exp, normalize ----------------
    {
        float a = 0.f;
        if (tid < 208) {
            a = expf(scp[2 * tid] + scp[2 * tid + 1]) * mk[tid];
            sc[tid] = a;
        }
        if (warp < 7) {
#pragma unroll
            for (int o = 16; o; o >>= 1) a += __shfl_xor_sync(0xffffffffu, a, o);
            if (lane == 0) red[warp] = a;
        }
    }
    __syncthreads();
    if (tid == 0) {
        float tsum = 0.f;
#pragma unroll
        for (int w = 0; w < 7; ++w) tsum += red[w];
        red[0] = 1.f / (tsum + 1e-7f);
    }
    __syncthreads();
    const float winv = red[0];

    // ---------------- Phase 5: out[b][d] = winv * sum_l sc[l] * x[l][d] ----------------
    {
        const int d = tid & 127;
        const int oct = tid >> 7;            // 0..7
        // x[l][d] lives at float index l*136 + 8*(d>>3) + 2*((d&7)&3) + ((d&7)>>2)
        const int r = d & 7;
        const int off = 8 * (d >> 3) + 2 * (r & 3) + (r >> 2);
        float a = 0.f;
        const int l0 = oct * 25;
#pragma unroll 5
        for (int l = l0; l < l0 + 25; ++l)
            a += sc[l] * xa[l * 136 + off];
        sm[OFF_WK + tid] = a;                // reuse Wk region (GEMM done)
    }
    __syncthreads();
    if (tid < 128) {
        float o = 0.f;
#pragma unroll
        for (int k = 0; k < 8; ++k) o += sm[OFF_WK + tid + 128 * k];
        out[(long long)b * 128 + tid] = o * winv;
    }
}

extern "C" void kernel_launch(void* const* d_in, const int* in_sizes, int n_in,
                              void* d_out, int out_size)
{
    const float* x  = (const float*)d_in[0];
    const float* q  = (const float*)d_in[1];
    const float* Wk = (const float*)d_in[2];
    const float* bk = (const float*)d_in[3];
    const float* Wq = (const float*)d_in[4];
    const float* v  = (const float*)d_in[5];
    float* out = (float*)d_out;

    const int B = in_sizes[1] / BB_D;  // q is [B, 128]

    pack_wk_kernel<<<26, 256>>>(Wk);

    cudaFuncSetAttribute(mxqa_mma_kernel, cudaFuncAttributeMaxDynamicSharedMemorySize, SMEM_BYTES);
    mxqa_mma_kernel<<<B, NT, SMEM_BYTES>>>(x, q, bk, Wq, v, out);
}